// round 1
// baseline (speedup 1.0000x reference)
#include <cuda_runtime.h>
#include <math.h>

#define MEM   1024
#define LSEQ  512
#define BATCH 128
#define INDIM 512
#define MROWS (BATCH * LSEQ)   /* 65536 */
#define NCOLS (2 * MEM)        /* 2048  */

/* scratch for soma_bias = 5*tanh(c1/5), laid out [b*LSEQ+t][m] (256 MiB) */
__device__ float g_sb[(size_t)MROWS * MEM];

/* ------------------------- GEMM: in_emb = u @ W^T + b, fused epilogue ----- */
#define BM 128
#define BN 128
#define BK 16
#define TM 8
#define TN 8

__global__ __launch_bounds__(256) void gemm_fused(
    const float* __restrict__ A,     /* u   [65536, 512] row-major      */
    const float* __restrict__ W,     /* W_im[2048, 512]  row-major (o,i) */
    const float* __restrict__ bias,  /* b_im[2048]                       */
    float* __restrict__ out_io)      /* d_out h_t region [65536, 1024]   */
{
    __shared__ float As[BK][BM];
    __shared__ float Bs[BK][BN];

    const int bn = blockIdx.x * BN;   /* output-column tile (o)      */
    const int bm = blockIdx.y * BM;   /* output-row tile (b*L + t)   */
    const int tid = threadIdx.x;
    const int tx = tid & 15;          /* 0..15 */
    const int ty = tid >> 4;          /* 0..15 */

    const int lrow = tid >> 2;        /* 0..63  (two rows: lrow, lrow+64) */
    const int lcol = (tid & 3) * 4;   /* 0,4,8,12 (k offset)              */

    float acc[TM][TN];
#pragma unroll
    for (int i = 0; i < TM; i++)
#pragma unroll
        for (int j = 0; j < TN; j++) acc[i][j] = 0.0f;

    for (int k0 = 0; k0 < INDIM; k0 += BK) {
        /* load A tile (128x16) and W tile (128x16), stored k-major in smem */
#pragma unroll
        for (int rr = 0; rr < 2; rr++) {
            const int r = lrow + rr * 64;
            float4 va = *(const float4*)&A[(size_t)(bm + r) * INDIM + k0 + lcol];
            As[lcol + 0][r] = va.x; As[lcol + 1][r] = va.y;
            As[lcol + 2][r] = va.z; As[lcol + 3][r] = va.w;
            float4 vb = *(const float4*)&W[(size_t)(bn + r) * INDIM + k0 + lcol];
            Bs[lcol + 0][r] = vb.x; Bs[lcol + 1][r] = vb.y;
            Bs[lcol + 2][r] = vb.z; Bs[lcol + 3][r] = vb.w;
        }
        __syncthreads();

#pragma unroll
        for (int kk = 0; kk < BK; kk++) {
            float4 a0 = *(const float4*)&As[kk][ty * TM];
            float4 a1 = *(const float4*)&As[kk][ty * TM + 4];
            float4 b0 = *(const float4*)&Bs[kk][tx * TN];
            float4 b1 = *(const float4*)&Bs[kk][tx * TN + 4];
            float a[TM] = {a0.x, a0.y, a0.z, a0.w, a1.x, a1.y, a1.z, a1.w};
            float b[TN] = {b0.x, b0.y, b0.z, b0.w, b1.x, b1.y, b1.z, b1.w};
#pragma unroll
            for (int i = 0; i < TM; i++)
#pragma unroll
                for (int j = 0; j < TN; j++)
                    acc[i][j] = fmaf(a[i], b[j], acc[i][j]);
        }
        __syncthreads();
    }

    /* epilogue: +bias; o<1024 -> soma_bias into scratch; o>=1024 -> io into d_out */
    float bj[TN];
#pragma unroll
    for (int j = 0; j < TN; j++) bj[j] = bias[bn + tx * TN + j];

    const bool is_sb = (bn < MEM);   /* whole block uniform: BN=128 divides 1024 */
#pragma unroll
    for (int i = 0; i < TM; i++) {
        const int row = bm + ty * TM + i;
        const size_t base = (size_t)row * MEM;
        if (is_sb) {
#pragma unroll
            for (int j = 0; j < TN; j++) {
                const int col = bn + tx * TN + j;
                float v = acc[i][j] + bj[j];
                g_sb[base + col] = 5.0f * tanhf(v / 5.0f);
            }
        } else {
#pragma unroll
            for (int j = 0; j < TN; j++) {
                const int col = bn + tx * TN + j;
                out_io[base + (col - MEM)] = acc[i][j] + bj[j];
            }
        }
    }
}

/* ------------------------- sequential scan over t ------------------------- */
/* One thread per (b, m) lane. Reads io (already in d_out) + sb (scratch),   */
/* overwrites io in place with hf. One-step prefetch to hide DRAM latency.   */
__global__ __launch_bounds__(256) void scan_kernel(
    const float* __restrict__ h0,   /* [2, 128, 1024] */
    float* __restrict__ out)        /* h_t [128,512,1024] then hf_last [128,1024] */
{
    const int g = blockIdx.x * blockDim.x + threadIdx.x;  /* 0..131071 */
    const int b = g >> 10;
    const int m = g & 1023;

    float hf = h0[(size_t)b * MEM + m];
    float hs = h0[(size_t)BATCH * MEM + (size_t)b * MEM + m];

    size_t idx = ((size_t)b * LSEQ) * MEM + m;
    float io = out[idx];
    float sb = g_sb[idx];

    for (int t = 0; t < LSEQ; t++) {
        float nio = 0.0f, nsb = 0.0f;
        if (t < LSEQ - 1) {
            nio = out[idx + MEM];
            nsb = g_sb[idx + MEM];
        }
        const float d = hs + 0.4f;
        const float hfn = tanhf(io + 4.0f * hf - 7.0f * d * d + sb);
        const float e = expf(-10.0f * (hf - 0.5f));
        const float eps = 0.9f + 0.9f / (1.0f + e);
        hs = (1.0f - eps) * hs + eps * hf;   /* uses OLD hf, OLD hs */
        hf = hfn;
        out[idx] = hfn;
        idx += MEM;
        io = nio; sb = nsb;
    }

    out[(size_t)MROWS * MEM + (size_t)b * MEM + m] = hf;  /* hf_last */
}

extern "C" void kernel_launch(void* const* d_in, const int* in_sizes, int n_in,
                              void* d_out, int out_size)
{
    const float* u    = (const float*)d_in[0];  /* [128,512,512]  */
    const float* h0   = (const float*)d_in[1];  /* [2,128,1024]   */
    const float* W    = (const float*)d_in[2];  /* [2048,512]     */
    const float* bias = (const float*)d_in[3];  /* [2048]         */
    float* out = (float*)d_out;

    dim3 grid(NCOLS / BN, MROWS / BM);          /* (16, 512): n-tile fastest -> W + A-tile L2 reuse */
    gemm_fused<<<grid, 256>>>(u, W, bias, out);

    scan_kernel<<<(BATCH * MEM) / 256, 256>>>(h0, out);
}

// round 4
// speedup vs baseline: 2.1536x; 2.1536x over previous
#include <cuda_runtime.h>
#include <cuda_bf16.h>
#include <cstdint>
#include <math.h>

#define MEM   1024
#define LSEQ  512
#define BATCH 128
#define INDIM 512
#define MROWS (BATCH * LSEQ)   /* 65536 */
#define NCOLS (2 * MEM)        /* 2048  */

/* ---- static scratch (no runtime allocation) ------------------------------ */
__device__ __align__(128) __nv_bfloat16 g_Abf[2ull * MROWS * INDIM]; /* hi|lo */
__device__ __align__(128) __nv_bfloat16 g_Wbf[2ull * NCOLS * INDIM]; /* hi|lo */
__device__ __align__(128) float g_sb[(size_t)MROWS * MEM];           /* soma_bias */

/* ------------------------------ PTX helpers ------------------------------ */
__device__ __forceinline__ uint32_t smem_u32(const void* p) {
    uint32_t a;
    asm("{ .reg .u64 t; cvta.to.shared.u64 t, %1; cvt.u32.u64 %0, t; }"
        : "=r"(a) : "l"(p));
    return a;
}
__device__ __forceinline__ void cp16(uint32_t dst, const void* src) {
    asm volatile("cp.async.cg.shared.global [%0], [%1], 16;" :: "r"(dst), "l"(src));
}
#define CP_COMMIT() asm volatile("cp.async.commit_group;" ::: "memory")
#define CP_WAIT1()  asm volatile("cp.async.wait_group 1;" ::: "memory")

__device__ __forceinline__ void ldsm4(uint32_t* r, uint32_t addr) {
    asm volatile("ldmatrix.sync.aligned.m8n8.x4.shared.b16 {%0,%1,%2,%3}, [%4];"
                 : "=r"(r[0]), "=r"(r[1]), "=r"(r[2]), "=r"(r[3]) : "r"(addr));
}
__device__ __forceinline__ void mma16816(float* c, const uint32_t* a,
                                         const uint32_t b0, const uint32_t b1) {
    asm volatile(
        "mma.sync.aligned.m16n8k16.row.col.f32.bf16.bf16.f32 "
        "{%0,%1,%2,%3}, {%4,%5,%6,%7}, {%8,%9}, {%0,%1,%2,%3};"
        : "+f"(c[0]), "+f"(c[1]), "+f"(c[2]), "+f"(c[3])
        : "r"(a[0]), "r"(a[1]), "r"(a[2]), "r"(a[3]), "r"(b0), "r"(b1));
}

/* ------------------- GEMM via mma.sync, split-bf16 (3 products) ---------- */
/* 128x128 tile, BK=32, K_eff = 3*512 = 1536 (planes: AhBh, AhBl, AlBh)      */
#define ROWB    80                      /* padded smem row: 64B data + 16B   */
#define TILE_B  (128 * ROWB)            /* 10240                             */
#define STAGE_B (2 * TILE_B)            /* A + B                             */
#define NSTG    3
#define BIAS_OFF (NSTG * STAGE_B)       /* 61440                             */
#define SMEM_SZ (BIAS_OFF + 512)
#define NITER   48                      /* 3 passes * 16 k-chunks            */

__global__ void __launch_bounds__(256, 2) gemm_mma(
    const float* __restrict__ bias, float* __restrict__ out_io)
{
    extern __shared__ char smem[];
    const uint32_t sb0 = smem_u32(smem);
    const int tid = threadIdx.x, wid = tid >> 5, lane = tid & 31;
    const int bn = blockIdx.x * 128, bm = blockIdx.y * 128;

    const __nv_bfloat16* Ah = g_Abf;
    const __nv_bfloat16* Al = g_Abf + (size_t)MROWS * INDIM;
    const __nv_bfloat16* Bh = g_Wbf;
    const __nv_bfloat16* Bl = g_Wbf + (size_t)NCOLS * INDIM;
    const __nv_bfloat16* APl[3] = { Ah, Ah, Al };
    const __nv_bfloat16* BPl[3] = { Bh, Bl, Bh };

    if (tid < 128) ((float*)(smem + BIAS_OFF))[tid] = bias[bn + tid];

    float acc[2][8][4];
#pragma unroll
    for (int i = 0; i < 2; i++)
#pragma unroll
        for (int j = 0; j < 8; j++)
#pragma unroll
            for (int q = 0; q < 4; q++) acc[i][j][q] = 0.0f;

    auto load_stage = [&](int it, int s) {
        const int p = it >> 4, ko = (it & 15) * 32;
        const __nv_bfloat16* As = APl[p] + (size_t)bm * INDIM + ko;
        const __nv_bfloat16* Bs = BPl[p] + (size_t)bn * INDIM + ko;
        const uint32_t dst = sb0 + s * STAGE_B;
#pragma unroll
        for (int j = 0; j < 2; j++) {
            const int id = tid + 256 * j;          /* 0..511 */
            const int row = id >> 2, un = id & 3;
            cp16(dst + row * ROWB + un * 16, As + (size_t)row * INDIM + un * 8);
            cp16(dst + TILE_B + row * ROWB + un * 16, Bs + (size_t)row * INDIM + un * 8);
        }
    };

    load_stage(0, 0); CP_COMMIT();
    load_stage(1, 1); CP_COMMIT();

    const int wm = (wid & 3) * 32;     /* warp m offset (4 warps)  */
    const int wn = (wid >> 2) * 64;    /* warp n offset (2 warps)  */
    const uint32_t lrow = (lane & 15) * ROWB + (lane >> 4) * 16;

    for (int it = 0; it < NITER; it++) {
        const int s = it % NSTG;
        CP_WAIT1();
        __syncthreads();
        if (it + 2 < NITER) load_stage(it + 2, (it + 2) % NSTG);
        CP_COMMIT();   /* unconditional: keeps group numbering aligned */

        const uint32_t aB = sb0 + s * STAGE_B + wm * ROWB + lrow;
        const uint32_t bB = sb0 + s * STAGE_B + TILE_B + wn * ROWB + lrow;
#pragma unroll
        for (int ks = 0; ks < 2; ks++) {
            uint32_t a[2][4], bq[4][4];
            ldsm4(a[0], aB + ks * 32);
            ldsm4(a[1], aB + 16 * ROWB + ks * 32);
#pragma unroll
            for (int pr = 0; pr < 4; pr++)
                ldsm4(bq[pr], bB + pr * 16 * ROWB + ks * 32);
#pragma unroll
            for (int mt = 0; mt < 2; mt++)
#pragma unroll
                for (int nt = 0; nt < 8; nt++)
                    mma16816(acc[mt][nt], a[mt],
                             bq[nt >> 1][nt & 1], bq[nt >> 1][(nt & 1) + 2]);
        }
    }
    __syncthreads();

    /* epilogue: +bias, optional tanh (soma_bias half), float2 stores */
    const float* bsh = (const float*)(smem + BIAS_OFF);
    const bool is_sb = (bn < MEM);
    float* ob = is_sb ? g_sb : out_io;
    const int cs = is_sb ? bn : (bn - MEM);

#pragma unroll
    for (int mt = 0; mt < 2; mt++) {
        const int r0 = bm + wm + mt * 16 + (lane >> 2);
#pragma unroll
        for (int nt = 0; nt < 8; nt++) {
            const int col = wn + nt * 8 + (lane & 3) * 2;
            const float b0 = bsh[col], b1 = bsh[col + 1];
            float2 v0, v1;
            v0.x = acc[mt][nt][0] + b0; v0.y = acc[mt][nt][1] + b1;
            v1.x = acc[mt][nt][2] + b0; v1.y = acc[mt][nt][3] + b1;
            if (is_sb) {
                v0.x = 5.0f * tanhf(v0.x * 0.2f); v0.y = 5.0f * tanhf(v0.y * 0.2f);
                v1.x = 5.0f * tanhf(v1.x * 0.2f); v1.y = 5.0f * tanhf(v1.y * 0.2f);
            }
            *(float2*)&ob[(size_t)r0 * MEM + cs + col] = v0;
            *(float2*)&ob[(size_t)(r0 + 8) * MEM + cs + col] = v1;
        }
    }
}

/* ------------------------- fp32 -> bf16 hi/lo split ---------------------- */
__device__ __forceinline__ void split4(const float4 v, __nv_bfloat162* hi2,
                                       __nv_bfloat162* lo2, size_t i) {
    __nv_bfloat16 hx = __float2bfloat16(v.x), hy = __float2bfloat16(v.y);
    __nv_bfloat16 hz = __float2bfloat16(v.z), hw = __float2bfloat16(v.w);
    __nv_bfloat162 h01; h01.x = hx; h01.y = hy;
    __nv_bfloat162 h23; h23.x = hz; h23.y = hw;
    __nv_bfloat162 l01, l23;
    l01.x = __float2bfloat16(v.x - __bfloat162float(hx));
    l01.y = __float2bfloat16(v.y - __bfloat162float(hy));
    l23.x = __float2bfloat16(v.z - __bfloat162float(hz));
    l23.y = __float2bfloat16(v.w - __bfloat162float(hw));
    hi2[2 * i] = h01; hi2[2 * i + 1] = h23;
    lo2[2 * i] = l01; lo2[2 * i + 1] = l23;
}

__global__ void __launch_bounds__(256) cvt_A(const float* __restrict__ src) {
    const size_t i = (size_t)blockIdx.x * 256 + threadIdx.x;
    float4 v = ((const float4*)src)[i];
    split4(v, (__nv_bfloat162*)g_Abf,
           (__nv_bfloat162*)(g_Abf + (size_t)MROWS * INDIM), i);
}
__global__ void __launch_bounds__(256) cvt_W(const float* __restrict__ src) {
    const size_t i = (size_t)blockIdx.x * 256 + threadIdx.x;
    float4 v = ((const float4*)src)[i];
    split4(v, (__nv_bfloat162*)g_Wbf,
           (__nv_bfloat162*)(g_Wbf + (size_t)NCOLS * INDIM), i);
}

/* ------------------------- sequential scan (float2, pf=2) ---------------- */
__device__ __forceinline__ void step1(float& hf, float& hs, float io, float sb) {
    const float d = hs + 0.4f;
    const float hfn = tanhf(io + 4.0f * hf - 7.0f * d * d + sb);
    const float e = expf(-10.0f * (hf - 0.5f));
    const float eps = 0.9f + 0.9f / (1.0f + e);
    hs = (1.0f - eps) * hs + eps * hf;
    hf = hfn;
}

__global__ void __launch_bounds__(256) scan2(const float* __restrict__ h0,
                                             float* __restrict__ out) {
    const int g = blockIdx.x * 256 + threadIdx.x;  /* 0..65535 */
    const int b = g >> 9;
    const int m2 = g & 511;

    const float2* h02 = (const float2*)h0;
    float2 hf = h02[(size_t)b * 512 + m2];
    float2 hs = h02[(size_t)BATCH * 512 + (size_t)b * 512 + m2];

    float2* out2 = (float2*)out;
    const float2* sb2 = (const float2*)g_sb;
    size_t idx = ((size_t)b * LSEQ) * 512 + m2;

    float2 io0 = out2[idx],       s0 = sb2[idx];
    float2 io1 = out2[idx + 512], s1 = sb2[idx + 512];

#pragma unroll 1
    for (int t = 0; t < LSEQ; t += 2) {
        float2 ni0 = {0.f, 0.f}, ns0 = ni0, ni1 = ni0, ns1 = ni0;
        if (t + 2 < LSEQ) { ni0 = out2[idx + 1024]; ns0 = sb2[idx + 1024]; }
        if (t + 3 < LSEQ) { ni1 = out2[idx + 1536]; ns1 = sb2[idx + 1536]; }

        step1(hf.x, hs.x, io0.x, s0.x);
        step1(hf.y, hs.y, io0.y, s0.y);
        out2[idx] = hf; idx += 512;

        step1(hf.x, hs.x, io1.x, s1.x);
        step1(hf.y, hs.y, io1.y, s1.y);
        out2[idx] = hf; idx += 512;

        io0 = ni0; s0 = ns0; io1 = ni1; s1 = ns1;
    }
    out2[(size_t)MROWS * 512 + (size_t)b * 512 + m2] = hf;  /* hf_last */
}

/* ------------------------------- launch ---------------------------------- */
extern "C" void kernel_launch(void* const* d_in, const int* in_sizes, int n_in,
                              void* d_out, int out_size)
{
    const float* u    = (const float*)d_in[0];  /* [128,512,512] */
    const float* h0   = (const float*)d_in[1];  /* [2,128,1024]  */
    const float* W    = (const float*)d_in[2];  /* [2048,512]    */
    const float* bias = (const float*)d_in[3];  /* [2048]        */
    float* out = (float*)d_out;

    cudaFuncSetAttribute(gemm_mma, cudaFuncAttributeMaxDynamicSharedMemorySize, SMEM_SZ);

    cvt_A<<<(MROWS * INDIM / 4) / 256, 256>>>(u);
    cvt_W<<<(NCOLS * INDIM / 4) / 256, 256>>>(W);
    gemm_mma<<<dim3(NCOLS / 128, MROWS / 128), 256, SMEM_SZ>>>(bias, out);
    scan2<<<(BATCH * MEM / 2) / 256, 256>>>(h0, out);
}